// round 3
// baseline (speedup 1.0000x reference)
#include <cuda_runtime.h>
#include <cuda_bf16.h>

#define NQ   16
#define DIM  65536
#define BATCH 32
#define TILE 16384
#define THREADS 512

// Fused per-(layer,qubit) 2x2 unitaries: [u00r,u00i,u01r,u01i,u10r,u10i,u11r,u11i]
__device__ float d_U[2][16][8];
// Scratch state (re/im) — static device globals (no runtime alloc)
__device__ float d_scr_re[BATCH * DIM];
__device__ float d_scr_im[BATCH * DIM];

// ---------------------------------------------------------------------------
// Fuse RZ(t2)*RY(t1)*RX(t0) per (layer, qubit). 32 threads.
// ---------------------------------------------------------------------------
__global__ void fuse_gates_kernel(const float* __restrict__ thetas) {
    int t = threadIdx.x;
    if (t >= 32) return;
    int l = t >> 4, q = t & 15;
    float th0 = thetas[l * 48 + 0 * 16 + q];
    float th1 = thetas[l * 48 + 1 * 16 + q];
    float th2 = thetas[l * 48 + 2 * 16 + q];
    float c0 = cosf(0.5f * th0), s0 = sinf(0.5f * th0);
    float c1 = cosf(0.5f * th1), s1 = sinf(0.5f * th1);
    float cz = cosf(0.5f * th2), sz = sinf(0.5f * th2);
    // M = RY * RX
    float m00r =  c1 * c0, m00i =  s1 * s0;
    float m01r = -s1 * c0, m01i = -c1 * s0;
    float m10r =  s1 * c0, m10i = -c1 * s0;
    float m11r =  c1 * c0, m11i = -s1 * s0;
    // U = RZ * M : row0 *= (cz - i sz), row1 *= (cz + i sz)
    float* u = d_U[l][q];
    u[0] = m00r * cz + m00i * sz;  u[1] = m00i * cz - m00r * sz;
    u[2] = m01r * cz + m01i * sz;  u[3] = m01i * cz - m01r * sz;
    u[4] = m10r * cz - m10i * sz;  u[5] = m10i * cz + m10r * sz;
    u[6] = m11r * cz - m11i * sz;  u[7] = m11i * cz + m11r * sz;
}

// ---------------------------------------------------------------------------
// In-tile helpers (local bit index space, tile = 2^14 amplitudes in smem)
// ---------------------------------------------------------------------------
__device__ __forceinline__ void apply1q(float* sre, float* sim, int j,
                                        const float* __restrict__ ug) {
    float u0 = ug[0], u1 = ug[1], u2 = ug[2], u3 = ug[3];
    float u4 = ug[4], u5 = ug[5], u6 = ug[6], u7 = ug[7];
    int mask = (1 << j) - 1;
    #pragma unroll 4
    for (int p = threadIdx.x; p < TILE / 2; p += THREADS) {
        int i0 = ((p & ~mask) << 1) | (p & mask);
        int i1 = i0 | (1 << j);
        float ar = sre[i0], ai = sim[i0];
        float br = sre[i1], bi = sim[i1];
        sre[i0] = u0 * ar - u1 * ai + u2 * br - u3 * bi;
        sim[i0] = u0 * ai + u1 * ar + u2 * bi + u3 * br;
        sre[i1] = u4 * ar - u5 * ai + u6 * br - u7 * bi;
        sim[i1] = u4 * ai + u5 * ar + u6 * bi + u7 * br;
    }
    __syncthreads();
}

__device__ __forceinline__ void cnot_s(float* sre, float* sim, int c, int t) {
    int lo = c < t ? c : t, hi = c < t ? t : c;
    int mlo = (1 << lo) - 1, mhi = (1 << hi) - 1;
    #pragma unroll 4
    for (int p = threadIdx.x; p < TILE / 4; p += THREADS) {
        int x = ((p & ~mlo) << 1) | (p & mlo);   // free bit lo
        x = ((x & ~mhi) << 1) | (x & mhi);       // free bit hi
        int i0 = x | (1 << c);                   // control=1, target=0
        int i1 = i0 | (1 << t);
        float tr = sre[i0]; sre[i0] = sre[i1]; sre[i1] = tr;
        float ti = sim[i0]; sim[i0] = sim[i1]; sim[i1] = ti;
    }
    __syncthreads();
}

// local tile index -> global index (within one state), per pass.
// PASS 1: in-set global bits 2..15, outer hv -> bits 0,1
// PASS 2: in-set {0,1,2,5..15},    outer hv -> bits 3,4
// PASS 3: in-set {0..5,8..15},     outer hv -> bits 6,7
template <int PASS>
__device__ __forceinline__ int map_idx(int l, int hv) {
    if (PASS == 1) return (l << 2) | hv;
    if (PASS == 2) return (l & 0x7) | (hv << 3) | ((l >> 3) << 5);
    return (l & 0x3F) | (hv << 6) | ((l >> 6) << 8);
}

template <int PASS>
__global__ void __launch_bounds__(THREADS, 1)
pass_kernel(const float* __restrict__ in_re, const float* __restrict__ in_im,
            float* __restrict__ probs) {
    extern __shared__ float sm[];
    float* sre = sm;
    float* sim = sm + TILE;
    int b = blockIdx.x >> 2;
    int hv = blockIdx.x & 3;
    int base = b * DIM;

    // ---- load tile ----
    if (PASS == 1) {
        for (int l = threadIdx.x; l < TILE; l += THREADS) {
            int gi = base + map_idx<PASS>(l, hv);
            sre[l] = in_re[gi];
            sim[l] = in_im[gi];
        }
    } else {
        for (int l = threadIdx.x; l < TILE; l += THREADS) {
            int gi = base + map_idx<PASS>(l, hv);
            sre[l] = d_scr_re[gi];
            sim[l] = d_scr_im[gi];
        }
    }
    __syncthreads();

    // ---- apply ops (qubit q <-> global bit 15-q) ----
    if (PASS == 1) {
        // L1 1q on global bits 2..15 = local bits 0..13: U[0][13 - k]
        for (int k = 0; k < 14; k++) apply1q(sre, sim, k, d_U[0][13 - k]);
        // L1 CNOT chain (15,14)..(3,2) global = local (13,12)..(1,0)
        for (int k = 13; k >= 1; k--) cnot_s(sre, sim, k, k - 1);
    } else if (PASS == 2) {
        // local bits: 0,1,2 -> global 0,1,2 ; local 3+t -> global 5+t
        apply1q(sre, sim, 1, d_U[0][14]);   // L1 1q on global bit 1 (q14)
        apply1q(sre, sim, 0, d_U[0][15]);   // L1 1q on global bit 0 (q15)
        cnot_s(sre, sim, 2, 1);             // L1 C(2,1)   (q13->q14)
        cnot_s(sre, sim, 1, 0);             // L1 C(1,0)   (q14->q15)
        cnot_s(sre, sim, 0, 13);            // L1 C(0,15)  (q15->q0)
        // L2 1q on in-set bits
        apply1q(sre, sim, 0, d_U[1][15]);
        apply1q(sre, sim, 1, d_U[1][14]);
        apply1q(sre, sim, 2, d_U[1][13]);
        for (int t = 0; t < 11; t++) apply1q(sre, sim, 3 + t, d_U[1][10 - t]);
        // L2 CNOT chain (15,14)..(6,5) global = local (13,12)..(4,3)
        for (int k = 13; k >= 4; k--) cnot_s(sre, sim, k, k - 1);
    } else {
        // local bits: 0..5 -> global 0..5 ; local 6+t -> global 8+t
        apply1q(sre, sim, 4, d_U[1][11]);   // L2 1q on global bit 4 (q11)
        apply1q(sre, sim, 3, d_U[1][12]);   // L2 1q on global bit 3 (q12)
        cnot_s(sre, sim, 5, 4);             // L2 C(5,4)
        cnot_s(sre, sim, 4, 3);             // L2 C(4,3)
        cnot_s(sre, sim, 3, 2);             // L2 C(3,2)
        cnot_s(sre, sim, 2, 1);             // L2 C(2,1)
        cnot_s(sre, sim, 1, 0);             // L2 C(1,0)
        cnot_s(sre, sim, 0, 13);            // L2 C(0,15): local 0 -> global 0, local 13 -> global 15
    }

    // ---- store tile ----
    if (PASS == 3) {
        for (int l = threadIdx.x; l < TILE; l += THREADS) {
            int gi = base + map_idx<PASS>(l, hv);
            float r = sre[l], i = sim[l];
            probs[gi] = r * r + i * i;
        }
    } else {
        for (int l = threadIdx.x; l < TILE; l += THREADS) {
            int gi = base + map_idx<PASS>(l, hv);
            d_scr_re[gi] = sre[l];
            d_scr_im[gi] = sim[l];
        }
    }
}

extern "C" void kernel_launch(void* const* d_in, const int* in_sizes, int n_in,
                              void* d_out, int out_size) {
    const float* thetas = (const float*)d_in[0];
    const float* st_re  = (const float*)d_in[1];
    const float* st_im  = (const float*)d_in[2];
    float* probs = (float*)d_out;

    const int SMEM = 2 * TILE * sizeof(float);  // 128 KB
    cudaFuncSetAttribute(pass_kernel<1>, cudaFuncAttributeMaxDynamicSharedMemorySize, SMEM);
    cudaFuncSetAttribute(pass_kernel<2>, cudaFuncAttributeMaxDynamicSharedMemorySize, SMEM);
    cudaFuncSetAttribute(pass_kernel<3>, cudaFuncAttributeMaxDynamicSharedMemorySize, SMEM);

    fuse_gates_kernel<<<1, 32>>>(thetas);
    dim3 grid(BATCH * 4);
    pass_kernel<1><<<grid, THREADS, SMEM>>>(st_re, st_im, probs);
    pass_kernel<2><<<grid, THREADS, SMEM>>>(st_re, st_im, probs);
    pass_kernel<3><<<grid, THREADS, SMEM>>>(st_re, st_im, probs);
}

// round 4
// speedup vs baseline: 1.9922x; 1.9922x over previous
#include <cuda_runtime.h>
#include <cuda_bf16.h>

#define DIM     65536
#define BATCH   32
#define TILE    16384
#define THREADS 512

// Fused per-(layer,qubit) 2x2 unitaries: [u00r,u00i,u01r,u01i,u10r,u10i,u11r,u11i]
__device__ float d_U[2][16][8];
__device__ float d_scr_re[BATCH * DIM];
__device__ float d_scr_im[BATCH * DIM];

__host__ __device__ constexpr int SWZ(int i) { return i ^ ((i >> 5) & 31); }

// ---------------------------------------------------------------------------
// Fuse RZ*RY*RX per (layer, qubit)
// ---------------------------------------------------------------------------
__global__ void fuse_gates_kernel(const float* __restrict__ thetas) {
    int t = threadIdx.x;
    if (t >= 32) return;
    int l = t >> 4, q = t & 15;
    float th0 = thetas[l * 48 + 0 * 16 + q];
    float th1 = thetas[l * 48 + 1 * 16 + q];
    float th2 = thetas[l * 48 + 2 * 16 + q];
    float c0 = cosf(0.5f * th0), s0 = sinf(0.5f * th0);
    float c1 = cosf(0.5f * th1), s1 = sinf(0.5f * th1);
    float cz = cosf(0.5f * th2), sz = sinf(0.5f * th2);
    float m00r =  c1 * c0, m00i =  s1 * s0;
    float m01r = -s1 * c0, m01i = -c1 * s0;
    float m10r =  s1 * c0, m10i = -c1 * s0;
    float m11r =  c1 * c0, m11i = -s1 * s0;
    float* u = d_U[l][q];
    u[0] = m00r * cz + m00i * sz;  u[1] = m00i * cz - m00r * sz;
    u[2] = m01r * cz + m01i * sz;  u[3] = m01i * cz - m01r * sz;
    u[4] = m10r * cz - m10i * sz;  u[5] = m10i * cz + m10r * sz;
    u[6] = m11r * cz - m11i * sz;  u[7] = m11i * cz + m11r * sz;
}

// ---------------------------------------------------------------------------
// Register-window machinery: thread holds 32 amps spanning window bits W0<..<W4
// ---------------------------------------------------------------------------
template <int WMASK>
__device__ __forceinline__ int expand_t(int t) {
    int base = 0, tb = 0;
    #pragma unroll
    for (int b = 0; b < 14; b++) {
        if (!(WMASK & (1 << b))) {
            base |= ((t >> tb) & 1) << b;
            tb++;
        }
    }
    return base;
}

template <int W0, int W1, int W2, int W3, int W4>
struct Sweep {
    static constexpr int WMASK = (1<<W0)|(1<<W1)|(1<<W2)|(1<<W3)|(1<<W4);
    int sbase;
    float ar[32], ai[32];

    static __device__ __forceinline__ constexpr int place(int r) {
        return (((r>>0)&1)<<W0)|(((r>>1)&1)<<W1)|(((r>>2)&1)<<W2)
             | (((r>>3)&1)<<W3)|(((r>>4)&1)<<W4);
    }
    __device__ __forceinline__ void ld(const float* sre, const float* sim) {
        sbase = SWZ(expand_t<WMASK>((int)threadIdx.x));
        #pragma unroll
        for (int r = 0; r < 32; r++) {
            int a = sbase ^ SWZ(place(r));     // XOR-linear swizzle, disjoint support
            ar[r] = sre[a];
            ai[r] = sim[a];
        }
    }
    __device__ __forceinline__ void st(float* sre, float* sim) {
        #pragma unroll
        for (int r = 0; r < 32; r++) {
            int a = sbase ^ SWZ(place(r));
            sre[a] = ar[r];
            sim[a] = ai[r];
        }
        __syncthreads();
    }
    // 1q gate on register-index bit KB (window position)
    template <int KB>
    __device__ __forceinline__ void g1q(const float* __restrict__ u) {
        float u0=u[0],u1=u[1],u2=u[2],u3=u[3],u4=u[4],u5=u[5],u6=u[6],u7=u[7];
        #pragma unroll
        for (int p = 0; p < 16; p++) {
            int lo = p & ((1 << KB) - 1);
            int i0 = ((p >> KB) << (KB + 1)) | lo;
            int i1 = i0 | (1 << KB);
            float xr = ar[i0], xi = ai[i0], yr = ar[i1], yi = ai[i1];
            ar[i0] = u0*xr - u1*xi + u2*yr - u3*yi;
            ai[i0] = u0*xi + u1*xr + u2*yi + u3*yr;
            ar[i1] = u4*xr - u5*xi + u6*yr - u7*yi;
            ai[i1] = u4*xi + u5*xr + u6*yi + u7*yr;
        }
    }
    // CNOT: control bit CB, target bit TB (window positions) — register permutation
    template <int CB, int TB>
    __device__ __forceinline__ void cx() {
        #pragma unroll
        for (int p = 0; p < 32; p++) {
            if (((p >> CB) & 1) && !((p >> TB) & 1)) {
                int q = p | (1 << TB);
                float tr = ar[p]; ar[p] = ar[q]; ar[q] = tr;
                float ti = ai[p]; ai[p] = ai[q]; ai[q] = ti;
            }
        }
    }
};

// local tile index -> global index (within one state) per pass (verified R2)
template <int PASS>
__device__ __forceinline__ int map_idx(int l, int hv) {
    if (PASS == 1) return (l << 2) | hv;
    if (PASS == 2) return (l & 0x7) | (hv << 3) | ((l >> 3) << 5);
    return (l & 0x3F) | (hv << 6) | ((l >> 6) << 8);
}

// ---------------------------------------------------------------------------
// Pass kernels (qubit q <-> global bit 15-q; op schedule verified in round 2)
// ---------------------------------------------------------------------------
__global__ void __launch_bounds__(THREADS, 1)
pass1_kernel(const float* __restrict__ in_re, const float* __restrict__ in_im) {
    extern __shared__ float sm[];
    float* sre = sm; float* sim = sm + TILE;
    int b = blockIdx.x >> 2, hv = blockIdx.x & 3, base = b * DIM;

    for (int l = threadIdx.x; l < TILE; l += THREADS) {
        int gi = base + map_idx<1>(l, hv);
        sre[SWZ(l)] = in_re[gi];
        sim[SWZ(l)] = in_im[gi];
    }
    __syncthreads();

    { // 1q bits 9..13 (U0[4..0]); C(13,12),C(12,11),C(11,10),C(10,9)
        Sweep<9,10,11,12,13> s; s.ld(sre, sim);
        s.g1q<0>(d_U[0][4]); s.g1q<1>(d_U[0][3]); s.g1q<2>(d_U[0][2]);
        s.g1q<3>(d_U[0][1]); s.g1q<4>(d_U[0][0]);
        s.cx<4,3>(); s.cx<3,2>(); s.cx<2,1>(); s.cx<1,0>();
        s.st(sre, sim);
    }
    { // 1q bits 5..8 (U0[8..5]); C(9,8)..C(6,5)
        Sweep<5,6,7,8,9> s; s.ld(sre, sim);
        s.g1q<0>(d_U[0][8]); s.g1q<1>(d_U[0][7]); s.g1q<2>(d_U[0][6]); s.g1q<3>(d_U[0][5]);
        s.cx<4,3>(); s.cx<3,2>(); s.cx<2,1>(); s.cx<1,0>();
        s.st(sre, sim);
    }
    { // 1q bits 1..4 (U0[12..9]); C(5,4)..C(2,1)
        Sweep<1,2,3,4,5> s; s.ld(sre, sim);
        s.g1q<0>(d_U[0][12]); s.g1q<1>(d_U[0][11]); s.g1q<2>(d_U[0][10]); s.g1q<3>(d_U[0][9]);
        s.cx<4,3>(); s.cx<3,2>(); s.cx<2,1>(); s.cx<1,0>();
        s.st(sre, sim);
    }
    { // 1q bit 0 (U0[13]); C(1,0)
        Sweep<0,1,2,3,4> s; s.ld(sre, sim);
        s.g1q<0>(d_U[0][13]);
        s.cx<1,0>();
        s.st(sre, sim);
    }

    for (int l = threadIdx.x; l < TILE; l += THREADS) {
        int gi = base + map_idx<1>(l, hv);
        d_scr_re[gi] = sre[SWZ(l)];
        d_scr_im[gi] = sim[SWZ(l)];
    }
}

__global__ void __launch_bounds__(THREADS, 1)
pass2_kernel() {
    extern __shared__ float sm[];
    float* sre = sm; float* sim = sm + TILE;
    int b = blockIdx.x >> 2, hv = blockIdx.x & 3, base = b * DIM;

    for (int l = threadIdx.x; l < TILE; l += THREADS) {
        int gi = base + map_idx<2>(l, hv);
        sre[SWZ(l)] = d_scr_re[gi];
        sim[SWZ(l)] = d_scr_im[gi];
    }
    __syncthreads();

    { // window {0,1,2,12,13} -> positions p0..p4 = bits 0,1,2,12,13
      // L1: 1q(1)=U0[14], 1q(0)=U0[15]; C(2,1); C(1,0); C(0,13)
      // L2: 1q(0)=U1[15],1q(1)=U1[14],1q(2)=U1[13],1q(12)=U1[1],1q(13)=U1[0]; C(13,12)
        Sweep<0,1,2,12,13> s; s.ld(sre, sim);
        s.g1q<1>(d_U[0][14]); s.g1q<0>(d_U[0][15]);
        s.cx<2,1>(); s.cx<1,0>(); s.cx<0,4>();
        s.g1q<0>(d_U[1][15]); s.g1q<1>(d_U[1][14]); s.g1q<2>(d_U[1][13]);
        s.g1q<3>(d_U[1][1]);  s.g1q<4>(d_U[1][0]);
        s.cx<4,3>();
        s.st(sre, sim);
    }
    { // 1q bits 8..11 (U1[5..2]); C(12,11)..C(9,8)
        Sweep<8,9,10,11,12> s; s.ld(sre, sim);
        s.g1q<0>(d_U[1][5]); s.g1q<1>(d_U[1][4]); s.g1q<2>(d_U[1][3]); s.g1q<3>(d_U[1][2]);
        s.cx<4,3>(); s.cx<3,2>(); s.cx<2,1>(); s.cx<1,0>();
        s.st(sre, sim);
    }
    { // 1q bits 4..7 (U1[9..6]); C(8,7)..C(5,4)
        Sweep<4,5,6,7,8> s; s.ld(sre, sim);
        s.g1q<0>(d_U[1][9]); s.g1q<1>(d_U[1][8]); s.g1q<2>(d_U[1][7]); s.g1q<3>(d_U[1][6]);
        s.cx<4,3>(); s.cx<3,2>(); s.cx<2,1>(); s.cx<1,0>();
        s.st(sre, sim);
    }
    { // 1q bit 3 (U1[10]); C(4,3)
        Sweep<0,1,2,3,4> s; s.ld(sre, sim);
        s.g1q<3>(d_U[1][10]);
        s.cx<4,3>();
        s.st(sre, sim);
    }

    for (int l = threadIdx.x; l < TILE; l += THREADS) {
        int gi = base + map_idx<2>(l, hv);
        d_scr_re[gi] = sre[SWZ(l)];
        d_scr_im[gi] = sim[SWZ(l)];
    }
}

__global__ void __launch_bounds__(THREADS, 1)
pass3_kernel(float* __restrict__ probs) {
    extern __shared__ float sm[];
    float* sre = sm; float* sim = sm + TILE;
    int b = blockIdx.x >> 2, hv = blockIdx.x & 3, base = b * DIM;

    for (int l = threadIdx.x; l < TILE; l += THREADS) {
        int gi = base + map_idx<3>(l, hv);
        sre[SWZ(l)] = d_scr_re[gi];
        sim[SWZ(l)] = d_scr_im[gi];
    }
    __syncthreads();

    { // 1q(4)=U1[11], 1q(3)=U1[12]; C(5,4),C(4,3),C(3,2),C(2,1)
        Sweep<1,2,3,4,5> s; s.ld(sre, sim);
        s.g1q<3>(d_U[1][11]); s.g1q<2>(d_U[1][12]);
        s.cx<4,3>(); s.cx<3,2>(); s.cx<2,1>(); s.cx<1,0>();
        s.st(sre, sim);
    }
    { // C(1,0); C(0,13)   (positions: bit0->p0, bit1->p1, bit13->p4)
        Sweep<0,1,2,12,13> s; s.ld(sre, sim);
        s.cx<1,0>(); s.cx<0,4>();
        s.st(sre, sim);
    }

    for (int l = threadIdx.x; l < TILE; l += THREADS) {
        int gi = base + map_idx<3>(l, hv);
        float r = sre[SWZ(l)], i = sim[SWZ(l)];
        probs[gi] = r * r + i * i;
    }
}

extern "C" void kernel_launch(void* const* d_in, const int* in_sizes, int n_in,
                              void* d_out, int out_size) {
    const float* thetas = (const float*)d_in[0];
    const float* st_re  = (const float*)d_in[1];
    const float* st_im  = (const float*)d_in[2];
    float* probs = (float*)d_out;

    const int SMEM = 2 * TILE * sizeof(float);  // 128 KB
    cudaFuncSetAttribute(pass1_kernel, cudaFuncAttributeMaxDynamicSharedMemorySize, SMEM);
    cudaFuncSetAttribute(pass2_kernel, cudaFuncAttributeMaxDynamicSharedMemorySize, SMEM);
    cudaFuncSetAttribute(pass3_kernel, cudaFuncAttributeMaxDynamicSharedMemorySize, SMEM);

    fuse_gates_kernel<<<1, 32>>>(thetas);
    dim3 grid(BATCH * 4);
    pass1_kernel<<<grid, THREADS, SMEM>>>(st_re, st_im);
    pass2_kernel<<<grid, THREADS, SMEM>>>();
    pass3_kernel<<<grid, THREADS, SMEM>>>(probs);
}

// round 5
// speedup vs baseline: 1.9933x; 1.0005x over previous
#include <cuda_runtime.h>
#include <cuda_bf16.h>

#define DIM     65536
#define BATCH   32
#define TILE    16384
#define THREADS 512

// Fused per-(layer,qubit) 2x2 unitaries: [u00r,u00i,u01r,u01i,u10r,u10i,u11r,u11i]
__device__ float d_U[2][16][8];
__device__ float d_scr_re[BATCH * DIM];
__device__ float d_scr_im[BATCH * DIM];

__host__ __device__ constexpr int SWZ(int i) { return i ^ ((i >> 5) & 31); }

// ---------------------------------------------------------------------------
// Fuse RZ*RY*RX per (layer, qubit)
// ---------------------------------------------------------------------------
__global__ void fuse_gates_kernel(const float* __restrict__ thetas) {
    int t = threadIdx.x;
    if (t >= 32) return;
    int l = t >> 4, q = t & 15;
    float th0 = thetas[l * 48 + 0 * 16 + q];
    float th1 = thetas[l * 48 + 1 * 16 + q];
    float th2 = thetas[l * 48 + 2 * 16 + q];
    float c0 = cosf(0.5f * th0), s0 = sinf(0.5f * th0);
    float c1 = cosf(0.5f * th1), s1 = sinf(0.5f * th1);
    float cz = cosf(0.5f * th2), sz = sinf(0.5f * th2);
    float m00r =  c1 * c0, m00i =  s1 * s0;
    float m01r = -s1 * c0, m01i = -c1 * s0;
    float m10r =  s1 * c0, m10i = -c1 * s0;
    float m11r =  c1 * c0, m11i = -s1 * s0;
    float* u = d_U[l][q];
    u[0] = m00r * cz + m00i * sz;  u[1] = m00i * cz - m00r * sz;
    u[2] = m01r * cz + m01i * sz;  u[3] = m01i * cz - m01r * sz;
    u[4] = m10r * cz - m10i * sz;  u[5] = m10i * cz + m10r * sz;
    u[6] = m11r * cz - m11i * sz;  u[7] = m11i * cz + m11r * sz;
}

// ---------------------------------------------------------------------------
// Register-window machinery: thread holds 32 amps spanning window bits W0<..<W4
// ---------------------------------------------------------------------------
template <int WMASK>
__device__ __forceinline__ int expand_t(int t) {
    int base = 0, tb = 0;
    #pragma unroll
    for (int b = 0; b < 14; b++) {
        if (!(WMASK & (1 << b))) {
            base |= ((t >> tb) & 1) << b;
            tb++;
        }
    }
    return base;
}

template <int W0, int W1, int W2, int W3, int W4>
struct Sweep {
    static constexpr int WMASK = (1<<W0)|(1<<W1)|(1<<W2)|(1<<W3)|(1<<W4);
    int sbase;
    float ar[32], ai[32];

    static __device__ __forceinline__ constexpr int place(int r) {
        return (((r>>0)&1)<<W0)|(((r>>1)&1)<<W1)|(((r>>2)&1)<<W2)
             | (((r>>3)&1)<<W3)|(((r>>4)&1)<<W4);
    }
    __device__ __forceinline__ void ld(const float* sre, const float* sim) {
        sbase = SWZ(expand_t<WMASK>((int)threadIdx.x));
        #pragma unroll
        for (int r = 0; r < 32; r++) {
            int a = sbase ^ SWZ(place(r));     // XOR-linear swizzle, disjoint support
            ar[r] = sre[a];
            ai[r] = sim[a];
        }
    }
    __device__ __forceinline__ void st(float* sre, float* sim) {
        #pragma unroll
        for (int r = 0; r < 32; r++) {
            int a = sbase ^ SWZ(place(r));
            sre[a] = ar[r];
            sim[a] = ai[r];
        }
        __syncthreads();
    }
    // 1q gate on register-index bit KB (window position)
    template <int KB>
    __device__ __forceinline__ void g1q(const float* __restrict__ u) {
        float u0=u[0],u1=u[1],u2=u[2],u3=u[3],u4=u[4],u5=u[5],u6=u[6],u7=u[7];
        #pragma unroll
        for (int p = 0; p < 16; p++) {
            int lo = p & ((1 << KB) - 1);
            int i0 = ((p >> KB) << (KB + 1)) | lo;
            int i1 = i0 | (1 << KB);
            float xr = ar[i0], xi = ai[i0], yr = ar[i1], yi = ai[i1];
            ar[i0] = u0*xr - u1*xi + u2*yr - u3*yi;
            ai[i0] = u0*xi + u1*xr + u2*yi + u3*yr;
            ar[i1] = u4*xr - u5*xi + u6*yr - u7*yi;
            ai[i1] = u4*xi + u5*xr + u6*yi + u7*yr;
        }
    }
    // CNOT: control bit CB, target bit TB (window positions) — register permutation
    template <int CB, int TB>
    __device__ __forceinline__ void cx() {
        #pragma unroll
        for (int p = 0; p < 32; p++) {
            if (((p >> CB) & 1) && !((p >> TB) & 1)) {
                int q = p | (1 << TB);
                float tr = ar[p]; ar[p] = ar[q]; ar[q] = tr;
                float ti = ai[p]; ai[p] = ai[q]; ai[q] = ti;
            }
        }
    }
};

// local tile index -> global index (within one state) per pass (verified R2)
template <int PASS>
__device__ __forceinline__ int map_idx(int l, int hv) {
    if (PASS == 1) return (l << 2) | hv;
    if (PASS == 2) return (l & 0x7) | (hv << 3) | ((l >> 3) << 5);
    return (l & 0x3F) | (hv << 6) | ((l >> 6) << 8);
}

// ---------------------------------------------------------------------------
// Pass kernels (qubit q <-> global bit 15-q; op schedule verified in round 2)
// ---------------------------------------------------------------------------
__global__ void __launch_bounds__(THREADS, 1)
pass1_kernel(const float* __restrict__ in_re, const float* __restrict__ in_im) {
    extern __shared__ float sm[];
    float* sre = sm; float* sim = sm + TILE;
    int b = blockIdx.x >> 2, hv = blockIdx.x & 3, base = b * DIM;

    for (int l = threadIdx.x; l < TILE; l += THREADS) {
        int gi = base + map_idx<1>(l, hv);
        sre[SWZ(l)] = in_re[gi];
        sim[SWZ(l)] = in_im[gi];
    }
    __syncthreads();

    { // 1q bits 9..13 (U0[4..0]); C(13,12),C(12,11),C(11,10),C(10,9)
        Sweep<9,10,11,12,13> s; s.ld(sre, sim);
        s.g1q<0>(d_U[0][4]); s.g1q<1>(d_U[0][3]); s.g1q<2>(d_U[0][2]);
        s.g1q<3>(d_U[0][1]); s.g1q<4>(d_U[0][0]);
        s.cx<4,3>(); s.cx<3,2>(); s.cx<2,1>(); s.cx<1,0>();
        s.st(sre, sim);
    }
    { // 1q bits 5..8 (U0[8..5]); C(9,8)..C(6,5)
        Sweep<5,6,7,8,9> s; s.ld(sre, sim);
        s.g1q<0>(d_U[0][8]); s.g1q<1>(d_U[0][7]); s.g1q<2>(d_U[0][6]); s.g1q<3>(d_U[0][5]);
        s.cx<4,3>(); s.cx<3,2>(); s.cx<2,1>(); s.cx<1,0>();
        s.st(sre, sim);
    }
    { // 1q bits 1..4 (U0[12..9]); C(5,4)..C(2,1)
        Sweep<1,2,3,4,5> s; s.ld(sre, sim);
        s.g1q<0>(d_U[0][12]); s.g1q<1>(d_U[0][11]); s.g1q<2>(d_U[0][10]); s.g1q<3>(d_U[0][9]);
        s.cx<4,3>(); s.cx<3,2>(); s.cx<2,1>(); s.cx<1,0>();
        s.st(sre, sim);
    }
    { // 1q bit 0 (U0[13]); C(1,0)
        Sweep<0,1,2,3,4> s; s.ld(sre, sim);
        s.g1q<0>(d_U[0][13]);
        s.cx<1,0>();
        s.st(sre, sim);
    }

    for (int l = threadIdx.x; l < TILE; l += THREADS) {
        int gi = base + map_idx<1>(l, hv);
        d_scr_re[gi] = sre[SWZ(l)];
        d_scr_im[gi] = sim[SWZ(l)];
    }
}

__global__ void __launch_bounds__(THREADS, 1)
pass2_kernel() {
    extern __shared__ float sm[];
    float* sre = sm; float* sim = sm + TILE;
    int b = blockIdx.x >> 2, hv = blockIdx.x & 3, base = b * DIM;

    for (int l = threadIdx.x; l < TILE; l += THREADS) {
        int gi = base + map_idx<2>(l, hv);
        sre[SWZ(l)] = d_scr_re[gi];
        sim[SWZ(l)] = d_scr_im[gi];
    }
    __syncthreads();

    { // window {0,1,2,12,13} -> positions p0..p4 = bits 0,1,2,12,13
      // L1: 1q(1)=U0[14], 1q(0)=U0[15]; C(2,1); C(1,0); C(0,13)
      // L2: 1q(0)=U1[15],1q(1)=U1[14],1q(2)=U1[13],1q(12)=U1[1],1q(13)=U1[0]; C(13,12)
        Sweep<0,1,2,12,13> s; s.ld(sre, sim);
        s.g1q<1>(d_U[0][14]); s.g1q<0>(d_U[0][15]);
        s.cx<2,1>(); s.cx<1,0>(); s.cx<0,4>();
        s.g1q<0>(d_U[1][15]); s.g1q<1>(d_U[1][14]); s.g1q<2>(d_U[1][13]);
        s.g1q<3>(d_U[1][1]);  s.g1q<4>(d_U[1][0]);
        s.cx<4,3>();
        s.st(sre, sim);
    }
    { // 1q bits 8..11 (U1[5..2]); C(12,11)..C(9,8)
        Sweep<8,9,10,11,12> s; s.ld(sre, sim);
        s.g1q<0>(d_U[1][5]); s.g1q<1>(d_U[1][4]); s.g1q<2>(d_U[1][3]); s.g1q<3>(d_U[1][2]);
        s.cx<4,3>(); s.cx<3,2>(); s.cx<2,1>(); s.cx<1,0>();
        s.st(sre, sim);
    }
    { // 1q bits 4..7 (U1[9..6]); C(8,7)..C(5,4)
        Sweep<4,5,6,7,8> s; s.ld(sre, sim);
        s.g1q<0>(d_U[1][9]); s.g1q<1>(d_U[1][8]); s.g1q<2>(d_U[1][7]); s.g1q<3>(d_U[1][6]);
        s.cx<4,3>(); s.cx<3,2>(); s.cx<2,1>(); s.cx<1,0>();
        s.st(sre, sim);
    }
    { // 1q bit 3 (U1[10]); C(4,3)
        Sweep<0,1,2,3,4> s; s.ld(sre, sim);
        s.g1q<3>(d_U[1][10]);
        s.cx<4,3>();
        s.st(sre, sim);
    }

    for (int l = threadIdx.x; l < TILE; l += THREADS) {
        int gi = base + map_idx<2>(l, hv);
        d_scr_re[gi] = sre[SWZ(l)];
        d_scr_im[gi] = sim[SWZ(l)];
    }
}

__global__ void __launch_bounds__(THREADS, 1)
pass3_kernel(float* __restrict__ probs) {
    extern __shared__ float sm[];
    float* sre = sm; float* sim = sm + TILE;
    int b = blockIdx.x >> 2, hv = blockIdx.x & 3, base = b * DIM;

    for (int l = threadIdx.x; l < TILE; l += THREADS) {
        int gi = base + map_idx<3>(l, hv);
        sre[SWZ(l)] = d_scr_re[gi];
        sim[SWZ(l)] = d_scr_im[gi];
    }
    __syncthreads();

    { // 1q(4)=U1[11], 1q(3)=U1[12]; C(5,4),C(4,3),C(3,2),C(2,1)
        Sweep<1,2,3,4,5> s; s.ld(sre, sim);
        s.g1q<3>(d_U[1][11]); s.g1q<2>(d_U[1][12]);
        s.cx<4,3>(); s.cx<3,2>(); s.cx<2,1>(); s.cx<1,0>();
        s.st(sre, sim);
    }
    { // C(1,0); C(0,13)   (positions: bit0->p0, bit1->p1, bit13->p4)
        Sweep<0,1,2,12,13> s; s.ld(sre, sim);
        s.cx<1,0>(); s.cx<0,4>();
        s.st(sre, sim);
    }

    for (int l = threadIdx.x; l < TILE; l += THREADS) {
        int gi = base + map_idx<3>(l, hv);
        float r = sre[SWZ(l)], i = sim[SWZ(l)];
        probs[gi] = r * r + i * i;
    }
}

extern "C" void kernel_launch(void* const* d_in, const int* in_sizes, int n_in,
                              void* d_out, int out_size) {
    const float* thetas = (const float*)d_in[0];
    const float* st_re  = (const float*)d_in[1];
    const float* st_im  = (const float*)d_in[2];
    float* probs = (float*)d_out;

    const int SMEM = 2 * TILE * sizeof(float);  // 128 KB
    cudaFuncSetAttribute(pass1_kernel, cudaFuncAttributeMaxDynamicSharedMemorySize, SMEM);
    cudaFuncSetAttribute(pass2_kernel, cudaFuncAttributeMaxDynamicSharedMemorySize, SMEM);
    cudaFuncSetAttribute(pass3_kernel, cudaFuncAttributeMaxDynamicSharedMemorySize, SMEM);

    fuse_gates_kernel<<<1, 32>>>(thetas);
    dim3 grid(BATCH * 4);
    pass1_kernel<<<grid, THREADS, SMEM>>>(st_re, st_im);
    pass2_kernel<<<grid, THREADS, SMEM>>>();
    pass3_kernel<<<grid, THREADS, SMEM>>>(probs);
}

// round 7
// speedup vs baseline: 2.7072x; 1.3581x over previous
#include <cuda_runtime.h>
#include <cuda_bf16.h>

#define DIM     65536
#define BATCH   32
#define TILE    16384
#define THREADS 512

// Scratch buffers (pass1->pass2 and pass2->pass3), custom layouts. Static: no runtime alloc.
__device__ float d_s1_re[BATCH * DIM], d_s1_im[BATCH * DIM];
__device__ float d_s2_re[BATCH * DIM], d_s2_im[BATCH * DIM];

__device__ __forceinline__ int SWZ(int i) { return i ^ ((i >> 5) & 31); }

// scr2 bit-permutation: a bits {0,6,7,8,9,5,1,2,3,4,10..13} -> addr bits {0..13}
__device__ __forceinline__ int PHI(int a) {
    return (a & 1) | (((a >> 6) & 15) << 1) | (((a >> 5) & 1) << 5)
         | (((a >> 1) & 15) << 6) | (a & 0x3C00);
}

// ---- address functors (replace device lambdas: no --extended-lambda flag) ----
struct MapS1Store {   // pass1 last window -> d_s1
    int cbase;
    __device__ __forceinline__ int operator()(int a) const {
        return cbase + ((a & 31) << 9) + (a >> 5);
    }
};
struct MapS1Load {    // pass2 first window <- d_s1
    int b4, hv3;
    __device__ __forceinline__ int operator()(int a) const {
        int o  = (a & 7) | hv3 | ((a >> 3) << 5);
        int a1 = o >> 2;
        return (b4 + (o & 3)) * TILE + ((a1 & 31) << 9) + (a1 >> 5);
    }
};
struct MapS2Store {   // pass2 last window -> d_s2
    int cbase;
    __device__ __forceinline__ int operator()(int a) const { return cbase + PHI(a); }
};
struct MapS2Load {    // pass3 first window <- d_s2
    int b4, hv6;
    __device__ __forceinline__ int operator()(int a) const {
        int o   = (a & 0x3F) | hv6 | ((a >> 6) << 8);
        int a2  = (o & 7) | ((o >> 5) << 3);
        int hv2 = (o >> 3) & 3;
        return (b4 + hv2) * TILE + PHI(a2);
    }
};

// ---------------------------------------------------------------------------
// Per-CTA fused unitaries U = RZ*RY*RX into smem: sU[(l*16+q)*8 + k]
// ---------------------------------------------------------------------------
__device__ __forceinline__ void compute_U(const float* __restrict__ thetas, float* sU) {
    int t = threadIdx.x;
    if (t < 32) {
        int l = t >> 4, q = t & 15;
        float th0 = thetas[l * 48 + 0 * 16 + q];
        float th1 = thetas[l * 48 + 1 * 16 + q];
        float th2 = thetas[l * 48 + 2 * 16 + q];
        float c0, s0, c1, s1, cz, sz;
        sincosf(0.5f * th0, &s0, &c0);
        sincosf(0.5f * th1, &s1, &c1);
        sincosf(0.5f * th2, &sz, &cz);
        float m00r =  c1 * c0, m00i =  s1 * s0;
        float m01r = -s1 * c0, m01i = -c1 * s0;
        float m10r =  s1 * c0, m10i = -c1 * s0;
        float m11r =  c1 * c0, m11i = -s1 * s0;
        float* u = sU + (l * 16 + q) * 8;
        u[0] = m00r * cz + m00i * sz;  u[1] = m00i * cz - m00r * sz;
        u[2] = m01r * cz + m01i * sz;  u[3] = m01i * cz - m01r * sz;
        u[4] = m10r * cz - m10i * sz;  u[5] = m10i * cz + m10r * sz;
        u[6] = m11r * cz - m11i * sz;  u[7] = m11i * cz + m11r * sz;
    }
    __syncthreads();
}

// ---------------------------------------------------------------------------
// Register window: thread holds 32 amps spanning tile-local bits W0<..<W4
// ---------------------------------------------------------------------------
template <int WMASK>
__device__ __forceinline__ int expand_t(int t) {
    int base = 0, tb = 0;
    #pragma unroll
    for (int b = 0; b < 14; b++) {
        if (!(WMASK & (1 << b))) { base |= ((t >> tb) & 1) << b; tb++; }
    }
    return base;
}

template <int W0, int W1, int W2, int W3, int W4>
struct Sweep {
    static constexpr int WMASK = (1<<W0)|(1<<W1)|(1<<W2)|(1<<W3)|(1<<W4);
    int sraw, sbase;
    float ar[32], ai[32];

    static __device__ __forceinline__ constexpr int place(int r) {
        return (((r>>0)&1)<<W0)|(((r>>1)&1)<<W1)|(((r>>2)&1)<<W2)
             | (((r>>3)&1)<<W3)|(((r>>4)&1)<<W4);
    }
    __device__ __forceinline__ void init() {
        sraw = expand_t<WMASK>((int)threadIdx.x);
        sbase = SWZ(sraw);
    }
    __device__ __forceinline__ void ld(const float* sre, const float* sim) {
        init();
        #pragma unroll
        for (int r = 0; r < 32; r++) {
            int a = sbase ^ SWZ(place(r));
            ar[r] = sre[a]; ai[r] = sim[a];
        }
    }
    __device__ __forceinline__ void st(float* sre, float* sim) {
        #pragma unroll
        for (int r = 0; r < 32; r++) {
            int a = sbase ^ SWZ(place(r));
            sre[a] = ar[r]; sim[a] = ai[r];
        }
        __syncthreads();
    }
    template <class F>
    __device__ __forceinline__ void ld_global(const float* gre, const float* gim, F f) {
        init();
        #pragma unroll
        for (int r = 0; r < 32; r++) {
            int gi = f(sraw | place(r));
            ar[r] = gre[gi]; ai[r] = gim[gi];
        }
    }
    template <class F>
    __device__ __forceinline__ void st_global(float* gre, float* gim, F f) {
        #pragma unroll
        for (int r = 0; r < 32; r++) {
            int gi = f(sraw | place(r));
            gre[gi] = ar[r]; gim[gi] = ai[r];
        }
    }
    template <int KB>
    __device__ __forceinline__ void g1q(const float* __restrict__ u) {
        float u0=u[0],u1=u[1],u2=u[2],u3=u[3],u4=u[4],u5=u[5],u6=u[6],u7=u[7];
        #pragma unroll
        for (int p = 0; p < 16; p++) {
            int lo = p & ((1 << KB) - 1);
            int i0 = ((p >> KB) << (KB + 1)) | lo;
            int i1 = i0 | (1 << KB);
            float xr = ar[i0], xi = ai[i0], yr = ar[i1], yi = ai[i1];
            ar[i0] = u0*xr - u1*xi + u2*yr - u3*yi;
            ai[i0] = u0*xi + u1*xr + u2*yi + u3*yr;
            ar[i1] = u4*xr - u5*xi + u6*yr - u7*yi;
            ai[i1] = u4*xi + u5*xr + u6*yi + u7*yr;
        }
    }
    template <int CB, int TB>
    __device__ __forceinline__ void cx() {
        #pragma unroll
        for (int p = 0; p < 32; p++) {
            if (((p >> CB) & 1) && !((p >> TB) & 1)) {
                int q = p | (1 << TB);
                float tr = ar[p]; ar[p] = ar[q]; ar[q] = tr;
                float ti = ai[p]; ai[p] = ai[q]; ai[q] = ti;
            }
        }
    }
};

#define SMEM_FLOATS (2 * TILE + 2 * 16 * 8)

// ---------------------------------------------------------------------------
// Pass 1: in-set pre-bits {2..15}, outer hv -> pre-bits {0,1}
// ---------------------------------------------------------------------------
__global__ void __launch_bounds__(THREADS, 1)
pass1_kernel(const float* __restrict__ thetas,
             const float* __restrict__ in_re, const float* __restrict__ in_im) {
    extern __shared__ float sm[];
    float* sre = sm; float* sim = sm + TILE; float* sU = sm + 2 * TILE;
    int b = blockIdx.x >> 2, hv = blockIdx.x & 3, base = b * DIM;

    // stage-in (L2-resident input) — overlapped with U compute
    for (int l = threadIdx.x; l < TILE; l += THREADS) {
        int gi = base + ((l << 2) | hv);
        sre[SWZ(l)] = in_re[gi];
        sim[SWZ(l)] = in_im[gi];
    }
    compute_U(thetas, sU);   // includes __syncthreads()

    { Sweep<9,10,11,12,13> s; s.ld(sre, sim);
      s.g1q<0>(sU+4*8); s.g1q<1>(sU+3*8); s.g1q<2>(sU+2*8);
      s.g1q<3>(sU+1*8); s.g1q<4>(sU+0*8);
      s.cx<4,3>(); s.cx<3,2>(); s.cx<2,1>(); s.cx<1,0>();
      s.st(sre, sim); }
    { Sweep<5,6,7,8,9> s; s.ld(sre, sim);
      s.g1q<0>(sU+8*8); s.g1q<1>(sU+7*8); s.g1q<2>(sU+6*8); s.g1q<3>(sU+5*8);
      s.cx<4,3>(); s.cx<3,2>(); s.cx<2,1>(); s.cx<1,0>();
      s.st(sre, sim); }
    { Sweep<1,2,3,4,5> s; s.ld(sre, sim);
      s.g1q<0>(sU+12*8); s.g1q<1>(sU+11*8); s.g1q<2>(sU+10*8); s.g1q<3>(sU+9*8);
      s.cx<4,3>(); s.cx<3,2>(); s.cx<2,1>(); s.cx<1,0>();
      s.st(sre, sim); }
    { Sweep<0,1,2,3,4> s; s.ld(sre, sim);
      s.g1q<0>(sU+13*8);
      s.cx<1,0>();
      MapS1Store f; f.cbase = (b * 4 + hv) * TILE;
      s.st_global(d_s1_re, d_s1_im, f); }
}

// ---------------------------------------------------------------------------
// Pass 2: in-set pre-bits {0,1,2,5..15}, outer hv -> pre-bits {3,4}
// ---------------------------------------------------------------------------
__global__ void __launch_bounds__(THREADS, 1)
pass2_kernel(const float* __restrict__ thetas) {
    extern __shared__ float sm[];
    float* sre = sm; float* sim = sm + TILE; float* sU = sm + 2 * TILE;
    int b = blockIdx.x >> 2, hv = blockIdx.x & 3;
    const float* U1 = sU + 16 * 8;

    compute_U(thetas, sU);

    { Sweep<0,1,2,12,13> s;
      MapS1Load f; f.b4 = b * 4; f.hv3 = hv << 3;
      s.ld_global(d_s1_re, d_s1_im, f);
      s.g1q<1>(sU+14*8); s.g1q<0>(sU+15*8);
      s.cx<2,1>(); s.cx<1,0>(); s.cx<0,4>();
      s.g1q<0>(U1+15*8); s.g1q<1>(U1+14*8); s.g1q<2>(U1+13*8);
      s.g1q<3>(U1+1*8);  s.g1q<4>(U1+0*8);
      s.cx<4,3>();
      s.st(sre, sim); }
    { Sweep<8,9,10,11,12> s; s.ld(sre, sim);
      s.g1q<0>(U1+5*8); s.g1q<1>(U1+4*8); s.g1q<2>(U1+3*8); s.g1q<3>(U1+2*8);
      s.cx<4,3>(); s.cx<3,2>(); s.cx<2,1>(); s.cx<1,0>();
      s.st(sre, sim); }
    { Sweep<4,5,6,7,8> s; s.ld(sre, sim);
      s.g1q<0>(U1+9*8); s.g1q<1>(U1+8*8); s.g1q<2>(U1+7*8); s.g1q<3>(U1+6*8);
      s.cx<4,3>(); s.cx<3,2>(); s.cx<2,1>(); s.cx<1,0>();
      s.st(sre, sim); }
    { Sweep<0,1,2,3,4> s; s.ld(sre, sim);
      s.g1q<3>(U1+10*8);
      s.cx<4,3>();
      MapS2Store f; f.cbase = (b * 4 + hv) * TILE;
      s.st_global(d_s2_re, d_s2_im, f); }
}

// ---------------------------------------------------------------------------
// Pass 3: in-set pre-bits {0..5,8..15}, outer hv -> pre-bits {6,7}
// ---------------------------------------------------------------------------
__global__ void __launch_bounds__(THREADS, 1)
pass3_kernel(const float* __restrict__ thetas, float* __restrict__ probs) {
    extern __shared__ float sm[];
    float* sre = sm; float* sim = sm + TILE; float* sU = sm + 2 * TILE;
    int b = blockIdx.x >> 2, hv = blockIdx.x & 3, base = b * DIM;
    const float* U1 = sU + 16 * 8;

    compute_U(thetas, sU);

    { Sweep<1,2,3,4,5> s;
      MapS2Load f; f.b4 = b * 4; f.hv6 = hv << 6;
      s.ld_global(d_s2_re, d_s2_im, f);
      s.g1q<3>(U1+11*8); s.g1q<2>(U1+12*8);
      s.cx<4,3>(); s.cx<3,2>(); s.cx<2,1>(); s.cx<1,0>();
      s.st(sre, sim); }
    { Sweep<0,1,2,12,13> s; s.ld(sre, sim);
      s.cx<1,0>(); s.cx<0,4>();
      // write |psi|^2 into sre at own amp slots (safe: per-window amp partition)
      #pragma unroll
      for (int r = 0; r < 32; r++) {
          int a = s.sbase ^ SWZ(s.place(r));
          sre[a] = s.ar[r] * s.ar[r] + s.ai[r] * s.ai[r];
      }
      __syncthreads(); }

    // coalesced read-out to probs
    for (int l = threadIdx.x; l < TILE; l += THREADS) {
        int gi = base + ((l & 0x3F) | (hv << 6) | ((l >> 6) << 8));
        probs[gi] = sre[SWZ(l)];
    }
}

extern "C" void kernel_launch(void* const* d_in, const int* in_sizes, int n_in,
                              void* d_out, int out_size) {
    const float* thetas = (const float*)d_in[0];
    const float* st_re  = (const float*)d_in[1];
    const float* st_im  = (const float*)d_in[2];
    float* probs = (float*)d_out;

    const int SMEM = SMEM_FLOATS * sizeof(float);  // 128 KB + 1 KB
    cudaFuncSetAttribute(pass1_kernel, cudaFuncAttributeMaxDynamicSharedMemorySize, SMEM);
    cudaFuncSetAttribute(pass2_kernel, cudaFuncAttributeMaxDynamicSharedMemorySize, SMEM);
    cudaFuncSetAttribute(pass3_kernel, cudaFuncAttributeMaxDynamicSharedMemorySize, SMEM);

    dim3 grid(BATCH * 4);
    pass1_kernel<<<grid, THREADS, SMEM>>>(thetas, st_re, st_im);
    pass2_kernel<<<grid, THREADS, SMEM>>>(thetas);
    pass3_kernel<<<grid, THREADS, SMEM>>>(thetas, probs);
}